// round 4
// baseline (speedup 1.0000x reference)
#include <cuda_runtime.h>

// LSTM_22763326669221 — fully fused big-batch tiny-LSTM, round 4.
// (Re-bench of round-3 design: round 3 failed on broker infrastructure,
// not on the kernel.)
// One thread = one batch element; h, c in registers across all 9 steps.
// Weights broadcast from shared via asm-volatile LDS (anti-LICM: R1/R2
// spilled ~9.7KB/thread because the compiler hoisted all loop-invariant
// shared weight loads out of the recurrence loops).

#define SEQB  3
#define BATCH 524288
#define INPD  2
#define HIDD  32
#define NCLS  2
#define FOUT  3

#define THREADS 128

typedef unsigned long long u64;

__device__ __forceinline__ u64 ffma2(u64 a, u64 b, u64 c) {
    u64 d;
    asm("fma.rn.f32x2 %0, %1, %2, %3;" : "=l"(d) : "l"(a), "l"(b), "l"(c));
    return d;
}
__device__ __forceinline__ u64 pk(float lo, float hi) {
    u64 r;
    asm("mov.b64 %0, {%1, %2};" : "=l"(r) : "f"(lo), "f"(hi));
    return r;
}
__device__ __forceinline__ void upk(u64 v, float& lo, float& hi) {
    asm("mov.b64 {%0, %1}, %2;" : "=f"(lo), "=f"(hi) : "l"(v));
}
// 16B shared load, not hoistable/CSE-able (asm volatile)
__device__ __forceinline__ void lds2(u64& a, u64& b, unsigned addr) {
    asm volatile("ld.shared.v2.b64 {%0, %1}, [%2];"
                 : "=l"(a), "=l"(b) : "r"(addr));
}
__device__ __forceinline__ u64 lds1(unsigned addr) {
    u64 v;
    asm volatile("ld.shared.b64 %0, [%1];" : "=l"(v) : "r"(addr));
    return v;
}
__device__ __forceinline__ float ex2f(float x) {
    float r; asm("ex2.approx.f32 %0, %1;" : "=f"(r) : "f"(x)); return r;
}
__device__ __forceinline__ float rcpf(float x) {
    float r; asm("rcp.approx.f32 %0, %1;" : "=f"(r) : "f"(x)); return r;
}
// sigmoid(x) = 1 / (1 + 2^(-x*log2e))  (2 MUFU)
__device__ __forceinline__ float sigmoidf(float x) {
    float t = ex2f(-1.4426950408889634f * x);
    return rcpf(1.0f + t);
}
// tanh(x): u = 2^(-2x*log2e); r = 1/(1+u); tanh = fma(-u, r, r)
__device__ __forceinline__ float tanhf_(float x) {
    float u = ex2f(-2.8853900817779268f * x);
    float r = rcpf(1.0f + u);
    return fmaf(-u, r, r);
}

// Shared layouts (u64 pair-packed, even/odd hidden units):
//  sW [p][kp][r], r = gate*2+par (gates i,f,g,o), row j = gate*32+2p+par
//                 value = (W_hh[j][2kp], W_hh[j][2kp+1])     16*16*8 u64
//  sIn[p][r][s] : s=0 -> (W_ih[j][0], W_ih[j][1]) ; s=1 -> (b[j], 0)
//  sFC[n][kp]   : (W_fc[n][2kp], W_fc[n][2kp+1]);  sFCb[n] = (b_fc[n], 0)

__global__ void __launch_bounds__(THREADS, 1)
lstm_fused_kernel(const float* __restrict__ x,
                  const float* __restrict__ W_ih,
                  const float* __restrict__ W_hh,
                  const float* __restrict__ b_ih,
                  const float* __restrict__ b_hh,
                  const float* __restrict__ W_fc,
                  const float* __restrict__ b_fc,
                  float* __restrict__ out) {
    __shared__ __align__(16) u64 sW[16 * 16 * 8];
    __shared__ __align__(16) u64 sIn[16 * 8 * 2];
    __shared__ __align__(16) u64 sFC[2 * 16];
    __shared__ __align__(16) u64 sFCb[2];

    for (int i = threadIdx.x; i < 16 * 16 * 8; i += THREADS) {
        int r = i & 7, kp = (i >> 3) & 15, p = i >> 7;
        int j = (r >> 1) * 32 + 2 * p + (r & 1);
        sW[i] = pk(W_hh[j * 32 + 2 * kp], W_hh[j * 32 + 2 * kp + 1]);
    }
    for (int i = threadIdx.x; i < 16 * 8 * 2; i += THREADS) {
        int s = i & 1, r = (i >> 1) & 7, p = i >> 4;
        int j = (r >> 1) * 32 + 2 * p + (r & 1);
        sIn[i] = s ? pk(b_ih[j] + b_hh[j], 0.0f)
                   : pk(W_ih[2 * j], W_ih[2 * j + 1]);
    }
    for (int i = threadIdx.x; i < 32; i += THREADS) {
        int n = i >> 4, kp = i & 15;
        sFC[i] = pk(W_fc[n * 32 + 2 * kp], W_fc[n * 32 + 2 * kp + 1]);
    }
    if (threadIdx.x < 2) sFCb[threadIdx.x] = pk(b_fc[threadIdx.x], 0.0f);
    __syncthreads();

    const unsigned sW_a  = (unsigned)__cvta_generic_to_shared(sW);
    const unsigned sIn_a = (unsigned)__cvta_generic_to_shared(sIn);
    const unsigned sFC_a = (unsigned)__cvta_generic_to_shared(sFC);
    const unsigned sFCb_a = (unsigned)__cvta_generic_to_shared(sFCb);

    const int e = blockIdx.x * THREADS + threadIdx.x;  // batch element

    const float2* x2 = reinterpret_cast<const float2*>(x);
    float2 v0 = x2[0 * BATCH + e];
    float2 v1 = x2[1 * BATCH + e];
    float2 v2 = x2[2 * BATCH + e];
    u64 d0 = pk(v0.x, v0.y);
    u64 d1 = pk(v1.x, v1.y);
    u64 d2 = pk(v2.x, v2.y);

    u64 h2[16], hn[16], c2[16];
#pragma unroll
    for (int k = 0; k < 16; k++) { h2[k] = 0ull; c2[k] = 0ull; }

    float2* o2 = reinterpret_cast<float2*>(out);

#pragma unroll 1
    for (int f = 0; f < FOUT; f++) {
#pragma unroll 1
        for (int t = 0; t < SEQB; t++) {
            u64 xp = (t == 0) ? d0 : ((t == 1) ? d1 : d2);
#pragma unroll
            for (int p = 0; p < 16; p++) {
                const unsigned wbase = sW_a + p * 1024;   // 16 kp * 8 r * 8B
                const unsigned ibase = sIn_a + p * 128;   // 8 r * 2 s * 8B
                u64 wih, bias;
                // accumulator init: lane.x = x0*wih0 + b ; lane.y = x1*wih1
                lds2(wih, bias, ibase + 0);   u64 a0 = ffma2(xp, wih, bias);
                lds2(wih, bias, ibase + 16);  u64 a1 = ffma2(xp, wih, bias);
                lds2(wih, bias, ibase + 32);  u64 a2 = ffma2(xp, wih, bias);
                lds2(wih, bias, ibase + 48);  u64 a3 = ffma2(xp, wih, bias);
                lds2(wih, bias, ibase + 64);  u64 a4 = ffma2(xp, wih, bias);
                lds2(wih, bias, ibase + 80);  u64 a5 = ffma2(xp, wih, bias);
                lds2(wih, bias, ibase + 96);  u64 a6 = ffma2(xp, wih, bias);
                lds2(wih, bias, ibase + 112); u64 a7 = ffma2(xp, wih, bias);
#pragma unroll
                for (int kp = 0; kp < 16; kp++) {
                    const unsigned ka = wbase + kp * 64;
                    u64 hh = h2[kp];
                    u64 w0, w1, w2, w3;
                    lds2(w0, w1, ka);
                    lds2(w2, w3, ka + 16);
                    a0 = ffma2(hh, w0, a0);
                    a1 = ffma2(hh, w1, a1);
                    a2 = ffma2(hh, w2, a2);
                    a3 = ffma2(hh, w3, a3);
                    lds2(w0, w1, ka + 32);
                    lds2(w2, w3, ka + 48);
                    a4 = ffma2(hh, w0, a4);
                    a5 = ffma2(hh, w1, a5);
                    a6 = ffma2(hh, w2, a6);
                    a7 = ffma2(hh, w3, a7);
                }
                float lo, hi;
                upk(a0, lo, hi); float gi0 = sigmoidf(lo + hi);
                upk(a1, lo, hi); float gi1 = sigmoidf(lo + hi);
                upk(a2, lo, hi); float gf0 = sigmoidf(lo + hi);
                upk(a3, lo, hi); float gf1 = sigmoidf(lo + hi);
                upk(a4, lo, hi); float gg0 = tanhf_(lo + hi);
                upk(a5, lo, hi); float gg1 = tanhf_(lo + hi);
                upk(a6, lo, hi); float go0 = sigmoidf(lo + hi);
                upk(a7, lo, hi); float go1 = sigmoidf(lo + hi);
                float c0, c1;
                upk(c2[p], c0, c1);
                float cn0 = fmaf(gf0, c0, gi0 * gg0);
                float cn1 = fmaf(gf1, c1, gi1 * gg1);
                c2[p] = pk(cn0, cn1);
                hn[p] = pk(go0 * tanhf_(cn0), go1 * tanhf_(cn1));
            }
#pragma unroll
            for (int k = 0; k < 16; k++) h2[k] = hn[k];
        }
        // FC head: out[n] = b_fc[n] + h . W_fc[n]
        u64 a0 = lds1(sFCb_a);
        u64 a1 = lds1(sFCb_a + 8);
#pragma unroll
        for (int kp = 0; kp < 16; kp += 2) {
            u64 w0, w1;
            lds2(w0, w1, sFC_a + kp * 8);
            a0 = ffma2(h2[kp], w0, a0);
            a0 = ffma2(h2[kp + 1], w1, a0);
            lds2(w0, w1, sFC_a + 128 + kp * 8);
            a1 = ffma2(h2[kp], w0, a1);
            a1 = ffma2(h2[kp + 1], w1, a1);
        }
        float p0, q0, p1, q1;
        upk(a0, p0, q0);
        upk(a1, p1, q1);
        float out0 = p0 + q0;
        float out1 = p1 + q1;
        o2[f * BATCH + e] = make_float2(out0, out1);
        // window update: data <- [data[2], data[1], output]
        d0 = d2;
        d2 = pk(out0, out1);
    }
}

extern "C" void kernel_launch(void* const* d_in, const int* in_sizes, int n_in,
                              void* d_out, int out_size) {
    const float* x    = (const float*)d_in[0];
    const float* W_ih = (const float*)d_in[1];
    const float* W_hh = (const float*)d_in[2];
    const float* b_ih = (const float*)d_in[3];
    const float* b_hh = (const float*)d_in[4];
    const float* W_fc = (const float*)d_in[5];
    const float* b_fc = (const float*)d_in[6];
    float* out = (float*)d_out;

    dim3 grid(BATCH / THREADS);
    lstm_fused_kernel<<<grid, THREADS>>>(x, W_ih, W_hh, b_ih, b_hh, W_fc, b_fc, out);
}

// round 5
// speedup vs baseline: 1.0831x; 1.0831x over previous
#include <cuda_runtime.h>

// LSTM_22763326669221 — fused big-batch tiny-LSTM, round 5.
// R4 passed at 1550us but was latency-bound: regs=245 -> occ 12.3%,
// issue 46%, because per-load `asm volatile` blocked load pipelining and
// bloated buffering. R5: launder shared base addresses once per step
// (blocks LICM/CSE across steps structurally) with plain reorderable
// LDS, and cap regs via launch_bounds(128,3) for 12 warps/SM.

#define SEQB  3
#define BATCH 524288
#define INPD  2
#define HIDD  32
#define NCLS  2
#define FOUT  3

#define THREADS 128

typedef unsigned long long u64;

__device__ __forceinline__ u64 ffma2(u64 a, u64 b, u64 c) {
    u64 d;
    asm("fma.rn.f32x2 %0, %1, %2, %3;" : "=l"(d) : "l"(a), "l"(b), "l"(c));
    return d;
}
__device__ __forceinline__ u64 pk(float lo, float hi) {
    u64 r;
    asm("mov.b64 %0, {%1, %2};" : "=l"(r) : "f"(lo), "f"(hi));
    return r;
}
__device__ __forceinline__ void upk(u64 v, float& lo, float& hi) {
    asm("mov.b64 {%0, %1}, %2;" : "=f"(lo), "=f"(hi) : "l"(v));
}
// Opaque pass-through: compiler must treat result as fresh each call.
__device__ __forceinline__ unsigned launder(unsigned a) {
    asm volatile("" : "+r"(a));
    return a;
}
// 16B shared load — plain (reorderable/pipelinable), guaranteed .v2.b64.
__device__ __forceinline__ void lds2(u64& a, u64& b, unsigned addr) {
    asm("ld.shared.v2.b64 {%0, %1}, [%2];"
        : "=l"(a), "=l"(b) : "r"(addr));
}
__device__ __forceinline__ u64 lds1(unsigned addr) {
    u64 v;
    asm("ld.shared.b64 %0, [%1];" : "=l"(v) : "r"(addr));
    return v;
}
__device__ __forceinline__ float ex2f(float x) {
    float r; asm("ex2.approx.f32 %0, %1;" : "=f"(r) : "f"(x)); return r;
}
__device__ __forceinline__ float rcpf(float x) {
    float r; asm("rcp.approx.f32 %0, %1;" : "=f"(r) : "f"(x)); return r;
}
// sigmoid(x) = 1 / (1 + 2^(-x*log2e))  (2 MUFU)
__device__ __forceinline__ float sigmoidf(float x) {
    float t = ex2f(-1.4426950408889634f * x);
    return rcpf(1.0f + t);
}
// tanh(x): u = 2^(-2x*log2e); r = 1/(1+u); tanh = fma(-u, r, r)
__device__ __forceinline__ float tanhf_(float x) {
    float u = ex2f(-2.8853900817779268f * x);
    float r = rcpf(1.0f + u);
    return fmaf(-u, r, r);
}

// Shared layouts (u64 pair-packed, even/odd hidden units):
//  sW [p][kp][r], r = gate*2+par (gates i,f,g,o), row j = gate*32+2p+par
//                 value = (W_hh[j][2kp], W_hh[j][2kp+1])     16*16*8 u64
//  sIn[p][r][s] : s=0 -> (W_ih[j][0], W_ih[j][1]) ; s=1 -> (b[j], 0)
//  sFC[n][kp]   : (W_fc[n][2kp], W_fc[n][2kp+1]);  sFCb[n] = (b_fc[n], 0)

__global__ void __launch_bounds__(THREADS, 3)
lstm_fused_kernel(const float* __restrict__ x,
                  const float* __restrict__ W_ih,
                  const float* __restrict__ W_hh,
                  const float* __restrict__ b_ih,
                  const float* __restrict__ b_hh,
                  const float* __restrict__ W_fc,
                  const float* __restrict__ b_fc,
                  float* __restrict__ out) {
    __shared__ __align__(16) u64 sW[16 * 16 * 8];
    __shared__ __align__(16) u64 sIn[16 * 8 * 2];
    __shared__ __align__(16) u64 sFC[2 * 16];
    __shared__ __align__(16) u64 sFCb[2];

    for (int i = threadIdx.x; i < 16 * 16 * 8; i += THREADS) {
        int r = i & 7, kp = (i >> 3) & 15, p = i >> 7;
        int j = (r >> 1) * 32 + 2 * p + (r & 1);
        sW[i] = pk(W_hh[j * 32 + 2 * kp], W_hh[j * 32 + 2 * kp + 1]);
    }
    for (int i = threadIdx.x; i < 16 * 8 * 2; i += THREADS) {
        int s = i & 1, r = (i >> 1) & 7, p = i >> 4;
        int j = (r >> 1) * 32 + 2 * p + (r & 1);
        sIn[i] = s ? pk(b_ih[j] + b_hh[j], 0.0f)
                   : pk(W_ih[2 * j], W_ih[2 * j + 1]);
    }
    for (int i = threadIdx.x; i < 32; i += THREADS) {
        int n = i >> 4, kp = i & 15;
        sFC[i] = pk(W_fc[n * 32 + 2 * kp], W_fc[n * 32 + 2 * kp + 1]);
    }
    if (threadIdx.x < 2) sFCb[threadIdx.x] = pk(b_fc[threadIdx.x], 0.0f);
    __syncthreads();

    const unsigned sW_a  = (unsigned)__cvta_generic_to_shared(sW);
    const unsigned sIn_a = (unsigned)__cvta_generic_to_shared(sIn);
    const unsigned sFC_a = (unsigned)__cvta_generic_to_shared(sFC);
    const unsigned sFCb_a = (unsigned)__cvta_generic_to_shared(sFCb);

    const int e = blockIdx.x * THREADS + threadIdx.x;  // batch element

    const float2* x2 = reinterpret_cast<const float2*>(x);
    float2 v0 = x2[0 * BATCH + e];
    float2 v1 = x2[1 * BATCH + e];
    float2 v2 = x2[2 * BATCH + e];
    u64 d0 = pk(v0.x, v0.y);
    u64 d1 = pk(v1.x, v1.y);
    u64 d2 = pk(v2.x, v2.y);

    u64 h2[16], hn[16], c2[16];
#pragma unroll
    for (int k = 0; k < 16; k++) { h2[k] = 0ull; c2[k] = 0ull; }

    float2* o2 = reinterpret_cast<float2*>(out);

#pragma unroll 1
    for (int f = 0; f < FOUT; f++) {
#pragma unroll 1
        for (int t = 0; t < SEQB; t++) {
            // Fresh (opaque) base addresses each step: loads below cannot be
            // hoisted or CSE'd across steps, but CAN be pipelined within one.
            const unsigned wA = launder(sW_a);
            const unsigned iA = launder(sIn_a);
            u64 xp = (t == 0) ? d0 : ((t == 1) ? d1 : d2);
#pragma unroll
            for (int p = 0; p < 16; p++) {
                const unsigned wbase = wA + p * 1024;   // 16 kp * 8 r * 8B
                const unsigned ibase = iA + p * 128;    // 8 r * 2 s * 8B
                u64 wih, bias;
                // accumulator init: lane.x = x0*wih0 + b ; lane.y = x1*wih1
                lds2(wih, bias, ibase + 0);   u64 a0 = ffma2(xp, wih, bias);
                lds2(wih, bias, ibase + 16);  u64 a1 = ffma2(xp, wih, bias);
                lds2(wih, bias, ibase + 32);  u64 a2 = ffma2(xp, wih, bias);
                lds2(wih, bias, ibase + 48);  u64 a3 = ffma2(xp, wih, bias);
                lds2(wih, bias, ibase + 64);  u64 a4 = ffma2(xp, wih, bias);
                lds2(wih, bias, ibase + 80);  u64 a5 = ffma2(xp, wih, bias);
                lds2(wih, bias, ibase + 96);  u64 a6 = ffma2(xp, wih, bias);
                lds2(wih, bias, ibase + 112); u64 a7 = ffma2(xp, wih, bias);
#pragma unroll
                for (int kp = 0; kp < 16; kp++) {
                    const unsigned ka = wbase + kp * 64;
                    u64 hh = h2[kp];
                    u64 w0, w1, w2, w3;
                    lds2(w0, w1, ka);
                    lds2(w2, w3, ka + 16);
                    a0 = ffma2(hh, w0, a0);
                    a1 = ffma2(hh, w1, a1);
                    a2 = ffma2(hh, w2, a2);
                    a3 = ffma2(hh, w3, a3);
                    lds2(w0, w1, ka + 32);
                    lds2(w2, w3, ka + 48);
                    a4 = ffma2(hh, w0, a4);
                    a5 = ffma2(hh, w1, a5);
                    a6 = ffma2(hh, w2, a6);
                    a7 = ffma2(hh, w3, a7);
                }
                float lo, hi;
                upk(a0, lo, hi); float gi0 = sigmoidf(lo + hi);
                upk(a1, lo, hi); float gi1 = sigmoidf(lo + hi);
                upk(a2, lo, hi); float gf0 = sigmoidf(lo + hi);
                upk(a3, lo, hi); float gf1 = sigmoidf(lo + hi);
                upk(a4, lo, hi); float gg0 = tanhf_(lo + hi);
                upk(a5, lo, hi); float gg1 = tanhf_(lo + hi);
                upk(a6, lo, hi); float go0 = sigmoidf(lo + hi);
                upk(a7, lo, hi); float go1 = sigmoidf(lo + hi);
                float c0, c1;
                upk(c2[p], c0, c1);
                float cn0 = fmaf(gf0, c0, gi0 * gg0);
                float cn1 = fmaf(gf1, c1, gi1 * gg1);
                c2[p] = pk(cn0, cn1);
                hn[p] = pk(go0 * tanhf_(cn0), go1 * tanhf_(cn1));
            }
#pragma unroll
            for (int k = 0; k < 16; k++) h2[k] = hn[k];
        }
        // FC head: out[n] = b_fc[n] + h . W_fc[n]
        const unsigned fA  = launder(sFC_a);
        const unsigned fbA = launder(sFCb_a);
        u64 a0 = lds1(fbA);
        u64 a1 = lds1(fbA + 8);
#pragma unroll
        for (int kp = 0; kp < 16; kp += 2) {
            u64 w0, w1;
            lds2(w0, w1, fA + kp * 8);
            a0 = ffma2(h2[kp], w0, a0);
            a0 = ffma2(h2[kp + 1], w1, a0);
            lds2(w0, w1, fA + 128 + kp * 8);
            a1 = ffma2(h2[kp], w0, a1);
            a1 = ffma2(h2[kp + 1], w1, a1);
        }
        float p0, q0, p1, q1;
        upk(a0, p0, q0);
        upk(a1, p1, q1);
        float out0 = p0 + q0;
        float out1 = p1 + q1;
        o2[f * BATCH + e] = make_float2(out0, out1);
        // window update: data <- [data[2], data[1], output]
        d0 = d2;
        d2 = pk(out0, out1);
    }
}

extern "C" void kernel_launch(void* const* d_in, const int* in_sizes, int n_in,
                              void* d_out, int out_size) {
    const float* x    = (const float*)d_in[0];
    const float* W_ih = (const float*)d_in[1];
    const float* W_hh = (const float*)d_in[2];
    const float* b_ih = (const float*)d_in[3];
    const float* b_hh = (const float*)d_in[4];
    const float* W_fc = (const float*)d_in[5];
    const float* b_fc = (const float*)d_in[6];
    float* out = (float*)d_out;

    dim3 grid(BATCH / THREADS);
    lstm_fused_kernel<<<grid, THREADS>>>(x, W_ih, W_hh, b_ih, b_hh, W_fc, b_fc, out);
}